// round 5
// baseline (speedup 1.0000x reference)
#include <cuda_runtime.h>
#include <cuda_bf16.h>
#include <math.h>

// Problem constants (fixed by the reference)
#define MAXN 100000
#define MAXE 1600000
#define IN_DIM 128
#define OUT_DIM 64
#define EDGE_DIM 32
#define NHEAD 4
#define HEADD 16

// Scratch (static device globals; no dynamic allocation allowed)
__device__ float g_feat_src[(size_t)MAXN * OUT_DIM];   // 25.6 MB
__device__ float g_feat_dst[(size_t)MAXN * OUT_DIM];   // 25.6 MB
__device__ float g_ex[(size_t)MAXE * NHEAD];           // 25.6 MB exp(logit)
__device__ float g_seg_sum[(size_t)MAXN * NHEAD];      // 1.6 MB

// Vectorized global reduction (sm_90+): 1 instruction for 4 floats
__device__ __forceinline__ void red_add_v4(float* addr, float x, float y, float z, float w) {
    asm volatile("red.global.add.v4.f32 [%0], {%1, %2, %3, %4};"
                 :: "l"(addr), "f"(x), "f"(y), "f"(z), "f"(w) : "memory");
}

// ---------------------------------------------------------------------------
// Kernel 0: init rst = bias (broadcast) and seg_sum = 0
// ---------------------------------------------------------------------------
__global__ void k_init(float* __restrict__ rst, const float* __restrict__ bias, int N) {
    int i = blockIdx.x * blockDim.x + threadIdx.x;
    int total = N * OUT_DIM;
    if (i < total) rst[i] = bias[i & (OUT_DIM - 1)];
    if (i < N * NHEAD) g_seg_sum[i] = 0.0f;
}

// ---------------------------------------------------------------------------
// Kernel 1 (fused): both node projections as one register-tiled GEMM.
//   C[n, j] = sum_k nf[n,k] * Wcat[j,k],  j in [0,128): j<64 -> W_src, else W_dst
// Block tile: 64 nodes x 128 outputs. 256 threads, each an 8x4 register tile.
// a-operand loaded as float4 (broadcast LDS.128) to halve smem wavefronts.
// ---------------------------------------------------------------------------
#define WS_PITCH 132
#define PROJ_SMEM_BYTES (IN_DIM * WS_PITCH * 4 + 64 * IN_DIM * 4)

__global__ void __launch_bounds__(256, 2)
k_node_proj_fused(const float* __restrict__ nf,
                  const float* __restrict__ W_src,
                  const float* __restrict__ W_dst,
                  int N) {
    extern __shared__ float sm[];
    float* Ws  = sm;                          // [128][WS_PITCH]
    float* nds = sm + IN_DIM * WS_PITCH;      // [64][128]

    int t = threadIdx.x;

    // Load both weight matrices transposed into Ws[k][j]
    for (int i = t; i < 128 * (IN_DIM / 4); i += 256) {
        int j  = i >> 5;
        int k4 = i & 31;
        float4 w = (j < 64)
            ? ((const float4*)W_src)[(size_t)j * (IN_DIM / 4) + k4]
            : ((const float4*)W_dst)[(size_t)(j - 64) * (IN_DIM / 4) + k4];
        int k = k4 * 4;
        Ws[(k + 0) * WS_PITCH + j] = w.x;
        Ws[(k + 1) * WS_PITCH + j] = w.y;
        Ws[(k + 2) * WS_PITCH + j] = w.z;
        Ws[(k + 3) * WS_PITCH + j] = w.w;
    }
    __syncthreads();

    int tx = t & 31;             // output quad index
    int ty = t >> 5;             // node group (0..7)
    int node_base_l = ty * 8;

    int ntiles = (N + 63) >> 6;
    for (int tile = blockIdx.x; tile < ntiles; tile += gridDim.x) {
        int node0 = tile * 64;

        // Cooperative load of 64 node rows (2048 float4), node-major
        for (int i = t; i < 64 * (IN_DIM / 4); i += 256) {
            int row = i >> 5;
            int k4  = i & 31;
            int node = node0 + row;
            float4 v = make_float4(0.f, 0.f, 0.f, 0.f);
            if (node < N)
                v = ((const float4*)nf)[(size_t)node * (IN_DIM / 4) + k4];
            ((float4*)(nds + row * IN_DIM))[k4] = v;
        }
        __syncthreads();

        float acc[8][4];
#pragma unroll
        for (int i = 0; i < 8; i++)
#pragma unroll
            for (int c = 0; c < 4; c++) acc[i][c] = 0.0f;

        const float* a0 = nds + node_base_l * IN_DIM;
#pragma unroll 2
        for (int k4 = 0; k4 < IN_DIM / 4; k4++) {
            float4 a4[8];
#pragma unroll
            for (int i = 0; i < 8; i++)
                a4[i] = *(const float4*)(a0 + i * IN_DIM + 4 * k4);
#pragma unroll
            for (int c = 0; c < 4; c++) {
                float4 b = *(const float4*)(Ws + (4 * k4 + c) * WS_PITCH + 4 * tx);
#pragma unroll
                for (int i = 0; i < 8; i++) {
                    float av = (c == 0) ? a4[i].x : (c == 1) ? a4[i].y
                             : (c == 2) ? a4[i].z : a4[i].w;
                    acc[i][0] += av * b.x;
                    acc[i][1] += av * b.y;
                    acc[i][2] += av * b.z;
                    acc[i][3] += av * b.w;
                }
            }
        }

        // Write out: tx < 16 -> feat_src cols 4tx..; tx >= 16 -> feat_dst
        {
            float* outbase = (tx < 16) ? g_feat_src : g_feat_dst;
            int jq = (tx < 16) ? tx : (tx - 16);
#pragma unroll
            for (int i = 0; i < 8; i++) {
                int node = node0 + node_base_l + i;
                if (node < N) {
                    float4 v = make_float4(acc[i][0], acc[i][1], acc[i][2], acc[i][3]);
                    ((float4*)(outbase + (size_t)node * OUT_DIM))[jq] = v;
                }
            }
        }
        __syncthreads();
    }
}

// ---------------------------------------------------------------------------
// Kernel 2: per-edge GATv2 logits + exp + segment-sum (denominator)
// Thread = (edge-pair, head): handles edges (le, le+64) of a 128-edge tile so
// each shared W-load feeds 2x the FMAs (smem-wavefront balanced vs fma pipe).
// ---------------------------------------------------------------------------
__global__ void __launch_bounds__(256)
k_edge_logits(const float* __restrict__ ef,
              const float* __restrict__ W_edge,
              const float* __restrict__ attn,
              const int* __restrict__ src,
              const int* __restrict__ dst,
              int E) {
    __shared__ float4 WeT4[EDGE_DIM * (OUT_DIM / 4)];   // [k][j4], 8 KB
    __shared__ float  attn_s[NHEAD * HEADD];            // 256 B
    __shared__ float4 efs[128][EDGE_DIM / 4];           // 16 KB
    __shared__ int    sidx[128], didx[128];

    for (int i = threadIdx.x; i < EDGE_DIM * OUT_DIM; i += blockDim.x) {
        int k = i >> 6;          // 0..31
        int j = i & 63;          // 0..63
        ((float*)WeT4)[i] = W_edge[(size_t)j * EDGE_DIM + k];
    }
    if (threadIdx.x < NHEAD * HEADD) attn_s[threadIdx.x] = attn[threadIdx.x];
    __syncthreads();

    int t = threadIdx.x;
    int le = t >> 2;             // local edge 0..63 (pair partner: le+64)
    int h  = t & 3;              // head

    int egroups = (E + 127) >> 7;
    for (int g = blockIdx.x; g < egroups; g += gridDim.x) {
        int ebase = g * 128;
        for (int i = t; i < 128 * (EDGE_DIM / 4); i += blockDim.x) {
            int lee = i >> 3;
            int k4  = i & 7;
            int e = ebase + lee;
            if (e < E)
                efs[lee][k4] = ((const float4*)ef)[(size_t)e * (EDGE_DIM / 4) + k4];
        }
        if (t < 128 && ebase + t < E) {
            sidx[t] = src[ebase + t];
            didx[t] = dst[ebase + t];
        }
        __syncthreads();

        int eA = ebase + le;
        int eB = eA + 64;
        bool vA = eA < E;
        bool vB = eB < E;
        int sA = vA ? sidx[le] : 0,      dA = vA ? didx[le] : 0;
        int sB = vB ? sidx[le + 64] : 0, dB = vB ? didx[le + 64] : 0;

        // Accumulators initialized with fs[src] + fd[dst] (L2-resident gathers)
        float4 A0, A1, A2, A3, B0, B1, B2, B3;
        {
            const float4* fsA = (const float4*)g_feat_src + (size_t)sA * (OUT_DIM / 4) + h * 4;
            const float4* fdA = (const float4*)g_feat_dst + (size_t)dA * (OUT_DIM / 4) + h * 4;
            const float4* fsB = (const float4*)g_feat_src + (size_t)sB * (OUT_DIM / 4) + h * 4;
            const float4* fdB = (const float4*)g_feat_dst + (size_t)dB * (OUT_DIM / 4) + h * 4;
            float4 x, y;
            x = fsA[0]; y = fdA[0]; A0 = make_float4(x.x + y.x, x.y + y.y, x.z + y.z, x.w + y.w);
            x = fsA[1]; y = fdA[1]; A1 = make_float4(x.x + y.x, x.y + y.y, x.z + y.z, x.w + y.w);
            x = fsA[2]; y = fdA[2]; A2 = make_float4(x.x + y.x, x.y + y.y, x.z + y.z, x.w + y.w);
            x = fsA[3]; y = fdA[3]; A3 = make_float4(x.x + y.x, x.y + y.y, x.z + y.z, x.w + y.w);
            x = fsB[0]; y = fdB[0]; B0 = make_float4(x.x + y.x, x.y + y.y, x.z + y.z, x.w + y.w);
            x = fsB[1]; y = fdB[1]; B1 = make_float4(x.x + y.x, x.y + y.y, x.z + y.z, x.w + y.w);
            x = fsB[2]; y = fdB[2]; B2 = make_float4(x.x + y.x, x.y + y.y, x.z + y.z, x.w + y.w);
            x = fsB[3]; y = fdB[3]; B3 = make_float4(x.x + y.x, x.y + y.y, x.z + y.z, x.w + y.w);
        }

        const float4* wrow = WeT4 + h * 4;   // [k][h*4 + dd]
#pragma unroll
        for (int k4 = 0; k4 < EDGE_DIM / 4; k4++) {
            float4 evA = efs[le][k4];
            float4 evB = efs[le + 64][k4];
#define EDGE_MAC2(compA, compB, kk)                                      \
            {                                                            \
                float va = compA, vb = compB;                            \
                float4 w0 = wrow[(kk) * 16 + 0];                         \
                float4 w1 = wrow[(kk) * 16 + 1];                         \
                float4 w2 = wrow[(kk) * 16 + 2];                         \
                float4 w3 = wrow[(kk) * 16 + 3];                         \
                A0.x += va * w0.x; A0.y += va * w0.y; A0.z += va * w0.z; A0.w += va * w0.w; \
                A1.x += va * w1.x; A1.y += va * w1.y; A1.z += va * w1.z; A1.w += va * w1.w; \
                A2.x += va * w2.x; A2.y += va * w2.y; A2.z += va * w2.z; A2.w += va * w2.w; \
                A3.x += va * w3.x; A3.y += va * w3.y; A3.z += va * w3.z; A3.w += va * w3.w; \
                B0.x += vb * w0.x; B0.y += vb * w0.y; B0.z += vb * w0.z; B0.w += vb * w0.w; \
                B1.x += vb * w1.x; B1.y += vb * w1.y; B1.z += vb * w1.z; B1.w += vb * w1.w; \
                B2.x += vb * w2.x; B2.y += vb * w2.y; B2.z += vb * w2.z; B2.w += vb * w2.w; \
                B3.x += vb * w3.x; B3.y += vb * w3.y; B3.z += vb * w3.z; B3.w += vb * w3.w; \
            }
            EDGE_MAC2(evA.x, evB.x, k4 * 4 + 0)
            EDGE_MAC2(evA.y, evB.y, k4 * 4 + 1)
            EDGE_MAC2(evA.z, evB.z, k4 * 4 + 2)
            EDGE_MAC2(evA.w, evB.w, k4 * 4 + 3)
#undef EDGE_MAC2
        }

        // leaky-relu + attn dot  (lrelu(x) = max(x, 0.2x))
        const float* lh = attn_s + h * HEADD;
        float logitA = 0.0f, logitB = 0.0f;
#define LK(lg, av, idx0)                                                 \
        lg += fmaxf(av.x, 0.2f * av.x) * lh[(idx0) + 0];                 \
        lg += fmaxf(av.y, 0.2f * av.y) * lh[(idx0) + 1];                 \
        lg += fmaxf(av.z, 0.2f * av.z) * lh[(idx0) + 2];                 \
        lg += fmaxf(av.w, 0.2f * av.w) * lh[(idx0) + 3];
        LK(logitA, A0, 0) LK(logitA, A1, 4) LK(logitA, A2, 8) LK(logitA, A3, 12)
        LK(logitB, B0, 0) LK(logitB, B1, 4) LK(logitB, B2, 8) LK(logitB, B3, 12)
#undef LK

        // exp without max-shift: alpha identical, fp32-safe (|logit| < ~35)
        if (vA) {
            float exl = __expf(logitA);
            g_ex[(size_t)eA * NHEAD + h] = exl;
            atomicAdd(&g_seg_sum[(size_t)dA * NHEAD + h], exl);
        }
        if (vB) {
            float exl = __expf(logitB);
            g_ex[(size_t)eB * NHEAD + h] = exl;
            atomicAdd(&g_seg_sum[(size_t)dB * NHEAD + h], exl);
        }
        __syncthreads();
    }
}

// ---------------------------------------------------------------------------
// Kernel 3: normalize alpha + aggregate, one thread per EDGE (all 4 heads).
// Vector loads: ex (float4), seg_sum row (float4); vector alpha store; 16x
// red.global.add.v4.f32 into rst[dst].
// ---------------------------------------------------------------------------
__global__ void k_aggregate(const int* __restrict__ src,
                            const int* __restrict__ dst,
                            float* __restrict__ rst,
                            float* __restrict__ alpha_out,   // may be null
                            int E) {
    int e = blockIdx.x * blockDim.x + threadIdx.x;
    if (e >= E) return;
    int s = src[e];
    int d = dst[e];

    float4 ex4 = *((const float4*)g_ex + e);
    float4 ss4 = *((const float4*)g_seg_sum + d);
    float4 al4 = make_float4(ex4.x / ss4.x, ex4.y / ss4.y,
                             ex4.z / ss4.z, ex4.w / ss4.w);
    if (alpha_out) ((float4*)alpha_out)[e] = al4;

    const float4* fs = (const float4*)g_feat_src + (size_t)s * (OUT_DIM / 4);
    float* ro = rst + (size_t)d * OUT_DIM;
    float ah[4] = {al4.x, al4.y, al4.z, al4.w};
#pragma unroll
    for (int h = 0; h < NHEAD; h++) {
        float a = ah[h];
#pragma unroll
        for (int dd = 0; dd < 4; dd++) {
            float4 v = fs[h * 4 + dd];
            red_add_v4(ro + h * HEADD + dd * 4, v.x * a, v.y * a, v.z * a, v.w * a);
        }
    }
}

// ---------------------------------------------------------------------------
// Launch
// ---------------------------------------------------------------------------
extern "C" void kernel_launch(void* const* d_in, const int* in_sizes, int n_in,
                              void* d_out, int out_size) {
    const float* node_feat = (const float*)d_in[0];
    const float* edge_feat = (const float*)d_in[1];
    const float* W_src     = (const float*)d_in[2];
    const float* W_dst     = (const float*)d_in[3];
    const float* W_edge    = (const float*)d_in[4];
    const float* attn      = (const float*)d_in[5];
    const float* bias      = (const float*)d_in[6];
    const int*   src       = (const int*)d_in[7];
    const int*   dst       = (const int*)d_in[8];

    int N = in_sizes[0] / IN_DIM;
    int E = in_sizes[1] / EDGE_DIM;

    float* rst = (float*)d_out;
    float* alpha_out = nullptr;
    if (out_size >= N * OUT_DIM + E * NHEAD)
        alpha_out = rst + (size_t)N * OUT_DIM;

    // K0: init output + seg_sum
    {
        int total = N * OUT_DIM;
        k_init<<<(total + 255) / 256, 256>>>(rst, bias, N);
    }
    // K1: fused dual node projection (dynamic smem > 48KB)
    {
        cudaFuncSetAttribute(k_node_proj_fused,
                             cudaFuncAttributeMaxDynamicSharedMemorySize,
                             PROJ_SMEM_BYTES);
        int ntiles = (N + 63) / 64;
        k_node_proj_fused<<<ntiles, 256, PROJ_SMEM_BYTES>>>(node_feat, W_src, W_dst, N);
    }
    // K2: edge logits + exp + segment sum (128-edge tiles, 2 edges/thread)
    k_edge_logits<<<2960, 256>>>(edge_feat, W_edge, attn, src, dst, E);
    // K3: normalize + aggregate (per-edge threads)
    k_aggregate<<<(E + 255) / 256, 256>>>(src, dst, rst, alpha_out, E);
}